// round 6
// baseline (speedup 1.0000x reference)
#include <cuda_runtime.h>
#include <cstdint>
#include <cstddef>

#define B_  2048
#define T_  256
#define D_  42
#define H_  64

typedef unsigned long long ull;

// 512MB scratch: gate-packed layer-0 preactivations, {(i,f),(g,o)} per (t,b,j)
__device__ ulonglong2 g_gx0[(size_t)B_ * T_ * H_];

// ---------------------------------------------------------------- helpers ---
__device__ __forceinline__ void fma2(ull& d, ull a, ull b) {
    // packed fp32x2 FMA: d = a*b + d  (two IEEE fp32 MACs per instruction)
    asm("fma.rn.f32x2 %0, %1, %2, %0;" : "+l"(d) : "l"(a), "l"(b));
}
__device__ __forceinline__ ull dup2(float v) {
    ull u = (ull)__float_as_uint(v); return u | (u << 32);
}
__device__ __forceinline__ ull pack2(float lo, float hi) {
    return (ull)__float_as_uint(lo) | ((ull)__float_as_uint(hi) << 32);
}
__device__ __forceinline__ float lo32(ull u) { return __uint_as_float((unsigned)u); }
__device__ __forceinline__ float hi32(ull u) { return __uint_as_float((unsigned)(u >> 32)); }
__device__ __forceinline__ float sigf(float x)   { return __fdividef(1.0f, 1.0f + __expf(-x)); }
__device__ __forceinline__ float tanhf_(float x) { float e = __expf(2.0f * x); return 1.0f - __fdividef(2.0f, e + 1.0f); }

// ============================================================================
// Prepass: gx0[t][b][j] = x[b,t,:] . W_ih0^T + b_ih0 + b_hh0   (gate-packed)
// 32 (b,t) rows per block; thread (j = tid&63, slot = tid>>6) does 8 rows.
// ============================================================================
#define PPX      34                             // x-dup pitch in ulls (even)
#define PP_SMEM  (D_ * H_ * 16 + D_ * PPX * 8)  // 43008 + 11424 = 54432 B

__global__ void __launch_bounds__(256, 2)
gx0_prepass(const float* __restrict__ x,
            const float* __restrict__ Wih0,
            const float* __restrict__ bih0,
            const float* __restrict__ bhh0)
{
    extern __shared__ char sm[];
    ulonglong2* Wp = (ulonglong2*)sm;            // [d*64 + j] {(i,f),(g,o)}
    ull*        xd = (ull*)(sm + D_ * H_ * 16);  // [d*PPX + row] duplicated x

    const int tid  = threadIdx.x;
    const int j    = tid & 63;
    const int slot = tid >> 6;                   // 0..3
    const int r0   = slot * 8;                   // first of this thread's 8 rows
    const size_t bt0 = (size_t)blockIdx.x * 32;

    for (int idx = tid; idx < D_ * H_; idx += 256) {
        int d = idx >> 6, jj = idx & 63;
        Wp[idx] = make_ulonglong2(
            pack2(Wih0[(jj      ) * D_ + d], Wih0[(jj +  64) * D_ + d]),
            pack2(Wih0[(jj + 128) * D_ + d], Wih0[(jj + 192) * D_ + d]));
    }
    for (int idx = tid; idx < 32 * D_; idx += 256) {
        int r = idx / D_, d = idx - r * D_;
        xd[d * PPX + r] = dup2(x[(bt0 + r) * D_ + d]);
    }
    const ull bif = pack2(bih0[j      ] + bhh0[j      ], bih0[j +  64] + bhh0[j +  64]);
    const ull bgo = pack2(bih0[j + 128] + bhh0[j + 128], bih0[j + 192] + bhh0[j + 192]);
    __syncthreads();

    ull aif[8], ago[8];
    #pragma unroll
    for (int r = 0; r < 8; r++) { aif[r] = bif; ago[r] = bgo; }

    #pragma unroll 6
    for (int d = 0; d < D_; d++) {
        ulonglong2 w = Wp[d * 64 + j];
        const ull* xr = &xd[d * PPX + r0];
        ulonglong2 xA = *(const ulonglong2*)&xr[0];
        ulonglong2 xB = *(const ulonglong2*)&xr[2];
        ulonglong2 xC = *(const ulonglong2*)&xr[4];
        ulonglong2 xD = *(const ulonglong2*)&xr[6];
        fma2(aif[0], w.x, xA.x); fma2(ago[0], w.y, xA.x);
        fma2(aif[1], w.x, xA.y); fma2(ago[1], w.y, xA.y);
        fma2(aif[2], w.x, xB.x); fma2(ago[2], w.y, xB.x);
        fma2(aif[3], w.x, xB.y); fma2(ago[3], w.y, xB.y);
        fma2(aif[4], w.x, xC.x); fma2(ago[4], w.y, xC.x);
        fma2(aif[5], w.x, xC.y); fma2(ago[5], w.y, xC.y);
        fma2(aif[6], w.x, xD.x); fma2(ago[6], w.y, xD.x);
        fma2(aif[7], w.x, xD.y); fma2(ago[7], w.y, xD.y);
    }
    #pragma unroll
    for (int r = 0; r < 8; r++) {
        size_t bt = bt0 + r0 + r;
        size_t b  = bt / T_;
        size_t t  = bt - b * T_;
        g_gx0[(t * B_ + b) * H_ + j] = make_ulonglong2(aif[r], ago[r]);
    }
}

// ============================================================================
// Recurrent kernel: 128 blocks x 16 rows, 256 threads.
// Thread (j = tid&63, rq = tid>>6) owns hidden unit j for rows rq*4..rq*4+3.
// h stored as {h,h} dups (ull); h0 double-buffered -> 2 barriers/step.
// ============================================================================
#define HP2       18                                     // h pitch in ulls (even)
#define HBUF      (64 * HP2)                             // 1152 ulls per buffer
#define SMEM_REC  (3 * 64 * 64 * 16 + 3 * HBUF * 8)      // 196608 + 27648 = 224256 B

__global__ void __launch_bounds__(256, 1)
lstm_rec(const float* __restrict__ Whh0,
         const float* __restrict__ Wih1,
         const float* __restrict__ Whh1,
         const float* __restrict__ bih1,
         const float* __restrict__ bhh1,
         const float* __restrict__ Wfc,
         const float* __restrict__ bfc,
         float* __restrict__ out)
{
    extern __shared__ char sm[];
    ulonglong2* W0p  = (ulonglong2*)sm;          // [k*64 + j], 64KB
    ulonglong2* W1ip = W0p  + 64 * 64;           // 64KB
    ulonglong2* W1hp = W1ip + 64 * 64;           // 64KB
    ull*        h0d  = (ull*)(W1hp + 64 * 64);   // 2 buffers of HBUF
    ull*        h1d  = h0d + 2 * HBUF;           // 1 buffer

    const int tid  = threadIdx.x;
    const int j    = tid & 63;
    const int rq   = tid >> 6;                   // 0..3
    const int base = blockIdx.x * 16;
    const int ro   = rq * 4;

    for (int idx = tid; idx < 64 * 64; idx += 256) {
        int k = idx >> 6, jj = idx & 63;
        W0p[idx]  = make_ulonglong2(
            pack2(Whh0[(jj      ) * 64 + k], Whh0[(jj +  64) * 64 + k]),
            pack2(Whh0[(jj + 128) * 64 + k], Whh0[(jj + 192) * 64 + k]));
        W1ip[idx] = make_ulonglong2(
            pack2(Wih1[(jj      ) * 64 + k], Wih1[(jj +  64) * 64 + k]),
            pack2(Wih1[(jj + 128) * 64 + k], Wih1[(jj + 192) * 64 + k]));
        W1hp[idx] = make_ulonglong2(
            pack2(Whh1[(jj      ) * 64 + k], Whh1[(jj +  64) * 64 + k]),
            pack2(Whh1[(jj + 128) * 64 + k], Whh1[(jj + 192) * 64 + k]));
    }
    const ull b1if = pack2(bih1[j      ] + bhh1[j      ], bih1[j +  64] + bhh1[j +  64]);
    const ull b1go = pack2(bih1[j + 128] + bhh1[j + 128], bih1[j + 192] + bhh1[j + 192]);
    for (int idx = tid; idx < 3 * HBUF; idx += 256) h0d[idx] = 0ull;  // h0 bufs + h1
    __syncthreads();

    float c0[4] = {0.f, 0.f, 0.f, 0.f};
    float c1[4] = {0.f, 0.f, 0.f, 0.f};

    ulonglong2 gx[4];
    #pragma unroll
    for (int r = 0; r < 4; r++)
        gx[r] = g_gx0[((size_t)base + ro + r) * H_ + j];     // t = 0

    for (int t = 0; t < T_; t++) {
        ulonglong2 gxn[4];
        if (t + 1 < T_) {
            #pragma unroll
            for (int r = 0; r < 4; r++)
                gxn[r] = g_gx0[((size_t)(t + 1) * B_ + base + ro + r) * H_ + j];
        }
        const ull* h0r = h0d + (t & 1) * HBUF;         // prev-step h0
        ull*       h0w = h0d + ((t & 1) ^ 1) * HBUF;   // this-step h0

        // ---------------- layer 0: gates = gx0 + W_hh0 . h0_prev ----------------
        ull aif[4], ago[4];
        #pragma unroll
        for (int r = 0; r < 4; r++) { aif[r] = gx[r].x; ago[r] = gx[r].y; }

        #pragma unroll 8
        for (int k = 0; k < 64; k++) {
            ulonglong2 w  = W0p[k * 64 + j];                          // lane-contig LDS.128
            ulonglong2 hA = *(const ulonglong2*)&h0r[k * HP2 + ro];   // broadcast
            ulonglong2 hB = *(const ulonglong2*)&h0r[k * HP2 + ro + 2];
            fma2(aif[0], w.x, hA.x); fma2(ago[0], w.y, hA.x);
            fma2(aif[1], w.x, hA.y); fma2(ago[1], w.y, hA.y);
            fma2(aif[2], w.x, hB.x); fma2(ago[2], w.y, hB.x);
            fma2(aif[3], w.x, hB.y); fma2(ago[3], w.y, hB.y);
        }
        float h0n[4];
        #pragma unroll
        for (int r = 0; r < 4; r++) {
            float i_ = sigf(lo32(aif[r])),  f_ = sigf(hi32(aif[r]));
            float g_ = tanhf_(lo32(ago[r])), o_ = sigf(hi32(ago[r]));
            c0[r]  = f_ * c0[r] + i_ * g_;
            h0n[r] = o_ * tanhf_(c0[r]);
        }
        // write to the OTHER buffer: no read-hazard with in-flight layer-0 reads
        *(ulonglong2*)&h0w[j * HP2 + ro]     = make_ulonglong2(dup2(h0n[0]), dup2(h0n[1]));
        *(ulonglong2*)&h0w[j * HP2 + ro + 2] = make_ulonglong2(dup2(h0n[2]), dup2(h0n[3]));
        __syncthreads();   // B1: new h0 visible to layer 1

        // -------- layer 1: gates = b1 + W_ih1 . h0_new + W_hh1 . h1_prev --------
        ull bif_[4], bgo_[4];
        #pragma unroll
        for (int r = 0; r < 4; r++) { bif_[r] = b1if; bgo_[r] = b1go; }

        #pragma unroll 4
        for (int k = 0; k < 64; k++) {
            ulonglong2 wi  = W1ip[k * 64 + j];
            ulonglong2 wh  = W1hp[k * 64 + j];
            ulonglong2 hA  = *(const ulonglong2*)&h0w[k * HP2 + ro];
            ulonglong2 hB  = *(const ulonglong2*)&h0w[k * HP2 + ro + 2];
            ulonglong2 pA  = *(const ulonglong2*)&h1d[k * HP2 + ro];
            ulonglong2 pB  = *(const ulonglong2*)&h1d[k * HP2 + ro + 2];
            fma2(bif_[0], wi.x, hA.x); fma2(bgo_[0], wi.y, hA.x);
            fma2(bif_[1], wi.x, hA.y); fma2(bgo_[1], wi.y, hA.y);
            fma2(bif_[2], wi.x, hB.x); fma2(bgo_[2], wi.y, hB.x);
            fma2(bif_[3], wi.x, hB.y); fma2(bgo_[3], wi.y, hB.y);
            fma2(bif_[0], wh.x, pA.x); fma2(bgo_[0], wh.y, pA.x);
            fma2(bif_[1], wh.x, pA.y); fma2(bgo_[1], wh.y, pA.y);
            fma2(bif_[2], wh.x, pB.x); fma2(bgo_[2], wh.y, pB.x);
            fma2(bif_[3], wh.x, pB.y); fma2(bgo_[3], wh.y, pB.y);
        }
        float h1n[4];
        #pragma unroll
        for (int r = 0; r < 4; r++) {
            float i_ = sigf(lo32(bif_[r])),  f_ = sigf(hi32(bif_[r]));
            float g_ = tanhf_(lo32(bgo_[r])), o_ = sigf(hi32(bgo_[r]));
            c1[r]  = f_ * c1[r] + i_ * g_;
            h1n[r] = o_ * tanhf_(c1[r]);
        }
        __syncthreads();   // B2: all layer-1 reads of old h1 (and h0w) done
        *(ulonglong2*)&h1d[j * HP2 + ro]     = make_ulonglong2(dup2(h1n[0]), dup2(h1n[1]));
        *(ulonglong2*)&h1d[j * HP2 + ro + 2] = make_ulonglong2(dup2(h1n[2]), dup2(h1n[3]));
        // h1 writes are made visible to next step's layer 1 by its B1.

        #pragma unroll
        for (int r = 0; r < 4; r++) gx[r] = gxn[r];
    }

    __syncthreads();       // final h1 visible for fc
    // ---------------- fc (64 -> 5) + softmax on final h1 ----------------
    if (tid < 16) {
        const int row = tid;
        const int b   = base + row;
        float lg[5];
        float mx = -1e30f;
        #pragma unroll
        for (int o = 0; o < 5; o++) {
            float s = bfc[o];
            #pragma unroll 8
            for (int k = 0; k < 64; k++)
                s += lo32(h1d[k * HP2 + row]) * Wfc[o * 64 + k];
            lg[o] = s;
            mx = fmaxf(mx, s);
        }
        float e[5], den = 0.0f;
        #pragma unroll
        for (int o = 0; o < 5; o++) { e[o] = __expf(lg[o] - mx); den += e[o]; }
        float inv = __fdividef(1.0f, den);
        #pragma unroll
        for (int o = 0; o < 5; o++) out[(size_t)b * 5 + o] = e[o] * inv;
    }
}

// ============================================================================
extern "C" void kernel_launch(void* const* d_in, const int* in_sizes, int n_in,
                              void* d_out, int out_size)
{
    const float* x    = (const float*)d_in[0];
    const float* Wih0 = (const float*)d_in[1];
    const float* Whh0 = (const float*)d_in[2];
    const float* bih0 = (const float*)d_in[3];
    const float* bhh0 = (const float*)d_in[4];
    const float* Wih1 = (const float*)d_in[5];
    const float* Whh1 = (const float*)d_in[6];
    const float* bih1 = (const float*)d_in[7];
    const float* bhh1 = (const float*)d_in[8];
    const float* Wfc  = (const float*)d_in[9];
    const float* bfc  = (const float*)d_in[10];
    float* out = (float*)d_out;

    cudaFuncSetAttribute(gx0_prepass, cudaFuncAttributeMaxDynamicSharedMemorySize, PP_SMEM);
    cudaFuncSetAttribute(lstm_rec,    cudaFuncAttributeMaxDynamicSharedMemorySize, SMEM_REC);

    gx0_prepass<<<(B_ * T_) / 32, 256, PP_SMEM>>>(x, Wih0, bih0, bhh0);
    lstm_rec<<<B_ / 16, 256, SMEM_REC>>>(Whh0, Wih1, Whh1, bih1, bhh1, Wfc, bfc, out);
}

// round 7
// speedup vs baseline: 1.1640x; 1.1640x over previous
#include <cuda_runtime.h>
#include <cstdint>
#include <cstddef>

#define B_  2048
#define T_  256
#define D_  42
#define H_  64

typedef unsigned long long ull;

// 512MB scratch: gate-packed layer-0 preactivations, {(i,f),(g,o)} per (t,b,j)
__device__ ulonglong2 g_gx0[(size_t)B_ * T_ * H_];

// ---------------------------------------------------------------- helpers ---
__device__ __forceinline__ void fma2(ull& d, ull a, ull b) {
    // packed fp32x2 FMA: d = a*b + d  (two IEEE fp32 MACs per instruction)
    asm("fma.rn.f32x2 %0, %1, %2, %0;" : "+l"(d) : "l"(a), "l"(b));
}
__device__ __forceinline__ ull dupf(float v) {
    // {v,v} pair built on the ALU pipe (2x MOV), keeps h in plain layout in smem
    unsigned r = __float_as_uint(v);
    ull d; asm("mov.b64 %0, {%1, %1};" : "=l"(d) : "r"(r));
    return d;
}
__device__ __forceinline__ ull dup2(float v) {
    ull u = (ull)__float_as_uint(v); return u | (u << 32);
}
__device__ __forceinline__ ull pack2(float lo, float hi) {
    return (ull)__float_as_uint(lo) | ((ull)__float_as_uint(hi) << 32);
}
__device__ __forceinline__ float lo32(ull u) { return __uint_as_float((unsigned)u); }
__device__ __forceinline__ float hi32(ull u) { return __uint_as_float((unsigned)(u >> 32)); }
__device__ __forceinline__ float sigf(float x)   { return __fdividef(1.0f, 1.0f + __expf(-x)); }
__device__ __forceinline__ float tanhf_(float x) { float e = __expf(2.0f * x); return 1.0f - __fdividef(2.0f, e + 1.0f); }

// ============================================================================
// Prepass: gx0[t][b][j] = x[b,t,:] . W_ih0^T + b_ih0 + b_hh0   (gate-packed)
// 32 (b,t) rows per block; thread (j = tid&63, slot = tid>>6) does 8 rows.
// ============================================================================
#define PPX      34                             // x-dup pitch in ulls (even)
#define PP_SMEM  (D_ * H_ * 16 + D_ * PPX * 8)  // 43008 + 11424 = 54432 B

__global__ void __launch_bounds__(256, 2)
gx0_prepass(const float* __restrict__ x,
            const float* __restrict__ Wih0,
            const float* __restrict__ bih0,
            const float* __restrict__ bhh0)
{
    extern __shared__ char sm[];
    ulonglong2* Wp = (ulonglong2*)sm;            // [d*64 + j] {(i,f),(g,o)}
    ull*        xd = (ull*)(sm + D_ * H_ * 16);  // [d*PPX + row] duplicated x

    const int tid  = threadIdx.x;
    const int j    = tid & 63;
    const int slot = tid >> 6;                   // 0..3
    const int r0   = slot * 8;                   // first of this thread's 8 rows
    const size_t bt0 = (size_t)blockIdx.x * 32;

    for (int idx = tid; idx < D_ * H_; idx += 256) {
        int d = idx >> 6, jj = idx & 63;
        Wp[idx] = make_ulonglong2(
            pack2(Wih0[(jj      ) * D_ + d], Wih0[(jj +  64) * D_ + d]),
            pack2(Wih0[(jj + 128) * D_ + d], Wih0[(jj + 192) * D_ + d]));
    }
    for (int idx = tid; idx < 32 * D_; idx += 256) {
        int r = idx / D_, d = idx - r * D_;
        xd[d * PPX + r] = dup2(x[(bt0 + r) * D_ + d]);
    }
    const ull bif = pack2(bih0[j      ] + bhh0[j      ], bih0[j +  64] + bhh0[j +  64]);
    const ull bgo = pack2(bih0[j + 128] + bhh0[j + 128], bih0[j + 192] + bhh0[j + 192]);
    __syncthreads();

    ull aif[8], ago[8];
    #pragma unroll
    for (int r = 0; r < 8; r++) { aif[r] = bif; ago[r] = bgo; }

    #pragma unroll 6
    for (int d = 0; d < D_; d++) {
        ulonglong2 w = Wp[d * 64 + j];
        const ull* xr = &xd[d * PPX + r0];
        ulonglong2 xA = *(const ulonglong2*)&xr[0];
        ulonglong2 xB = *(const ulonglong2*)&xr[2];
        ulonglong2 xC = *(const ulonglong2*)&xr[4];
        ulonglong2 xD = *(const ulonglong2*)&xr[6];
        fma2(aif[0], w.x, xA.x); fma2(ago[0], w.y, xA.x);
        fma2(aif[1], w.x, xA.y); fma2(ago[1], w.y, xA.y);
        fma2(aif[2], w.x, xB.x); fma2(ago[2], w.y, xB.x);
        fma2(aif[3], w.x, xB.y); fma2(ago[3], w.y, xB.y);
        fma2(aif[4], w.x, xC.x); fma2(ago[4], w.y, xC.x);
        fma2(aif[5], w.x, xC.y); fma2(ago[5], w.y, xC.y);
        fma2(aif[6], w.x, xD.x); fma2(ago[6], w.y, xD.x);
        fma2(aif[7], w.x, xD.y); fma2(ago[7], w.y, xD.y);
    }
    #pragma unroll
    for (int r = 0; r < 8; r++) {
        size_t bt = bt0 + r0 + r;
        size_t b  = bt / T_;
        size_t t  = bt - b * T_;
        g_gx0[(t * B_ + b) * H_ + j] = make_ulonglong2(aif[r], ago[r]);
    }
}

// ============================================================================
// Recurrent kernel: 128 blocks x 16 rows, 256 threads.
// Thread (j = tid&63, rq = tid>>6) owns hidden unit j for rows rq*4..rq*4+3.
// h stored PLAIN ([k*HP + row], pitch 20 floats, conflict-free float4 I/O);
// f32x2 operand dups built in registers (ALU pipe). h0 double-buffered.
// ============================================================================
#define HP        20                                     // h pitch in floats
#define HBUF      (64 * HP)                              // floats per buffer
#define SMEM_REC  (3 * 64 * 64 * 16 + 3 * HBUF * 4)      // 196608 + 15360 = 211968 B

__global__ void __launch_bounds__(256, 1)
lstm_rec(const float* __restrict__ Whh0,
         const float* __restrict__ Wih1,
         const float* __restrict__ Whh1,
         const float* __restrict__ bih1,
         const float* __restrict__ bhh1,
         const float* __restrict__ Wfc,
         const float* __restrict__ bfc,
         float* __restrict__ out)
{
    extern __shared__ char sm[];
    ulonglong2* W0p  = (ulonglong2*)sm;          // [k*64 + j], 64KB
    ulonglong2* W1ip = W0p  + 64 * 64;           // 64KB
    ulonglong2* W1hp = W1ip + 64 * 64;           // 64KB
    float*      h0d  = (float*)(W1hp + 64 * 64); // 2 buffers of HBUF
    float*      h1d  = h0d + 2 * HBUF;           // 1 buffer

    const int tid  = threadIdx.x;
    const int j    = tid & 63;
    const int rq   = tid >> 6;                   // 0..3
    const int base = blockIdx.x * 16;
    const int ro   = rq * 4;

    for (int idx = tid; idx < 64 * 64; idx += 256) {
        int k = idx >> 6, jj = idx & 63;
        W0p[idx]  = make_ulonglong2(
            pack2(Whh0[(jj      ) * 64 + k], Whh0[(jj +  64) * 64 + k]),
            pack2(Whh0[(jj + 128) * 64 + k], Whh0[(jj + 192) * 64 + k]));
        W1ip[idx] = make_ulonglong2(
            pack2(Wih1[(jj      ) * 64 + k], Wih1[(jj +  64) * 64 + k]),
            pack2(Wih1[(jj + 128) * 64 + k], Wih1[(jj + 192) * 64 + k]));
        W1hp[idx] = make_ulonglong2(
            pack2(Whh1[(jj      ) * 64 + k], Whh1[(jj +  64) * 64 + k]),
            pack2(Whh1[(jj + 128) * 64 + k], Whh1[(jj + 192) * 64 + k]));
    }
    const ull b1if = pack2(bih1[j      ] + bhh1[j      ], bih1[j +  64] + bhh1[j +  64]);
    const ull b1go = pack2(bih1[j + 128] + bhh1[j + 128], bih1[j + 192] + bhh1[j + 192]);
    for (int idx = tid; idx < 3 * HBUF; idx += 256) h0d[idx] = 0.0f;  // h0 bufs + h1
    __syncthreads();

    float c0[4] = {0.f, 0.f, 0.f, 0.f};
    float c1[4] = {0.f, 0.f, 0.f, 0.f};

    ulonglong2 gx[4];
    #pragma unroll
    for (int r = 0; r < 4; r++)
        gx[r] = g_gx0[((size_t)base + ro + r) * H_ + j];     // t = 0

    for (int t = 0; t < T_; t++) {
        ulonglong2 gxn[4];
        if (t + 1 < T_) {
            #pragma unroll
            for (int r = 0; r < 4; r++)
                gxn[r] = g_gx0[((size_t)(t + 1) * B_ + base + ro + r) * H_ + j];
        }
        const float* h0r = h0d + (t & 1) * HBUF;         // prev-step h0
        float*       h0w = h0d + ((t & 1) ^ 1) * HBUF;   // this-step h0

        // ---------------- layer 0: gates = gx0 + W_hh0 . h0_prev ----------------
        ull aif[4], ago[4];
        #pragma unroll
        for (int r = 0; r < 4; r++) { aif[r] = gx[r].x; ago[r] = gx[r].y; }

        #pragma unroll 8
        for (int k = 0; k < 64; k++) {
            ulonglong2 w  = W0p[k * 64 + j];                 // lane-contig LDS.128
            float4     hv = *(const float4*)&h0r[k * HP + ro]; // warp-uniform bcast
            ull d0 = dupf(hv.x), d1 = dupf(hv.y), d2 = dupf(hv.z), d3 = dupf(hv.w);
            fma2(aif[0], w.x, d0); fma2(ago[0], w.y, d0);
            fma2(aif[1], w.x, d1); fma2(ago[1], w.y, d1);
            fma2(aif[2], w.x, d2); fma2(ago[2], w.y, d2);
            fma2(aif[3], w.x, d3); fma2(ago[3], w.y, d3);
        }
        float h0n[4];
        #pragma unroll
        for (int r = 0; r < 4; r++) {
            float i_ = sigf(lo32(aif[r])),  f_ = sigf(hi32(aif[r]));
            float g_ = tanhf_(lo32(ago[r])), o_ = sigf(hi32(ago[r]));
            c0[r]  = f_ * c0[r] + i_ * g_;
            h0n[r] = o_ * tanhf_(c0[r]);
        }
        // write to the OTHER buffer: no read-hazard with in-flight layer-0 reads
        *(float4*)&h0w[j * HP + ro] = make_float4(h0n[0], h0n[1], h0n[2], h0n[3]);
        __syncthreads();   // B1: new h0 visible to layer 1

        // -------- layer 1: gates = b1 + W_ih1 . h0_new + W_hh1 . h1_prev --------
        ull bif_[4], bgo_[4];
        #pragma unroll
        for (int r = 0; r < 4; r++) { bif_[r] = b1if; bgo_[r] = b1go; }

        #pragma unroll 4
        for (int k = 0; k < 64; k++) {
            ulonglong2 wi = W1ip[k * 64 + j];
            ulonglong2 wh = W1hp[k * 64 + j];
            float4 h0v = *(const float4*)&h0w[k * HP + ro];
            float4 h1v = *(const float4*)&h1d[k * HP + ro];
            ull e0 = dupf(h0v.x), e1 = dupf(h0v.y), e2 = dupf(h0v.z), e3 = dupf(h0v.w);
            ull p0 = dupf(h1v.x), p1 = dupf(h1v.y), p2 = dupf(h1v.z), p3 = dupf(h1v.w);
            fma2(bif_[0], wi.x, e0); fma2(bgo_[0], wi.y, e0);
            fma2(bif_[1], wi.x, e1); fma2(bgo_[1], wi.y, e1);
            fma2(bif_[2], wi.x, e2); fma2(bgo_[2], wi.y, e2);
            fma2(bif_[3], wi.x, e3); fma2(bgo_[3], wi.y, e3);
            fma2(bif_[0], wh.x, p0); fma2(bgo_[0], wh.y, p0);
            fma2(bif_[1], wh.x, p1); fma2(bgo_[1], wh.y, p1);
            fma2(bif_[2], wh.x, p2); fma2(bgo_[2], wh.y, p2);
            fma2(bif_[3], wh.x, p3); fma2(bgo_[3], wh.y, p3);
        }
        float h1n[4];
        #pragma unroll
        for (int r = 0; r < 4; r++) {
            float i_ = sigf(lo32(bif_[r])),  f_ = sigf(hi32(bif_[r]));
            float g_ = tanhf_(lo32(bgo_[r])), o_ = sigf(hi32(bgo_[r]));
            c1[r]  = f_ * c1[r] + i_ * g_;
            h1n[r] = o_ * tanhf_(c1[r]);
        }
        __syncthreads();   // B2: all layer-1 reads of old h1 (and h0w) done
        *(float4*)&h1d[j * HP + ro] = make_float4(h1n[0], h1n[1], h1n[2], h1n[3]);
        // h1 writes are made visible to next step's layer 1 by its B1.

        #pragma unroll
        for (int r = 0; r < 4; r++) gx[r] = gxn[r];
    }

    __syncthreads();       // final h1 visible for fc
    // ---------------- fc (64 -> 5) + softmax on final h1 ----------------
    if (tid < 16) {
        const int row = tid;
        const int b   = base + row;
        float lg[5];
        float mx = -1e30f;
        #pragma unroll
        for (int o = 0; o < 5; o++) {
            float s = bfc[o];
            #pragma unroll 8
            for (int k = 0; k < 64; k++)
                s += h1d[k * HP + row] * Wfc[o * 64 + k];
            lg[o] = s;
            mx = fmaxf(mx, s);
        }
        float e[5], den = 0.0f;
        #pragma unroll
        for (int o = 0; o < 5; o++) { e[o] = __expf(lg[o] - mx); den += e[o]; }
        float inv = __fdividef(1.0f, den);
        #pragma unroll
        for (int o = 0; o < 5; o++) out[(size_t)b * 5 + o] = e[o] * inv;
    }
}

// ============================================================================
extern "C" void kernel_launch(void* const* d_in, const int* in_sizes, int n_in,
                              void* d_out, int out_size)
{
    const float* x    = (const float*)d_in[0];
    const float* Wih0 = (const float*)d_in[1];
    const float* Whh0 = (const float*)d_in[2];
    const float* bih0 = (const float*)d_in[3];
    const float* bhh0 = (const float*)d_in[4];
    const float* Wih1 = (const float*)d_in[5];
    const float* Whh1 = (const float*)d_in[6];
    const float* bih1 = (const float*)d_in[7];
    const float* bhh1 = (const float*)d_in[8];
    const float* Wfc  = (const float*)d_in[9];
    const float* bfc  = (const float*)d_in[10];
    float* out = (float*)d_out;

    cudaFuncSetAttribute(gx0_prepass, cudaFuncAttributeMaxDynamicSharedMemorySize, PP_SMEM);
    cudaFuncSetAttribute(lstm_rec,    cudaFuncAttributeMaxDynamicSharedMemorySize, SMEM_REC);

    gx0_prepass<<<(B_ * T_) / 32, 256, PP_SMEM>>>(x, Wih0, bih0, bhh0);
    lstm_rec<<<B_ / 16, 256, SMEM_REC>>>(Whh0, Wih1, Whh1, bih1, bhh1, Wfc, bfc, out);
}